// round 17
// baseline (speedup 1.0000x reference)
#include <cuda_runtime.h>
#include <cuda_fp16.h>
#include <math.h>
#include <stdint.h>

// Problem shapes (fixed by the dataset)
#define B_ROWS 16384
#define DK     512
#define NKEYS  4096
#define DV     512
#define NH     32
#define TAU_MIN 0.1f
#define TAU_MAX 5.0f
#define EPSF    1e-8f

// Scratch (never passed from host — selector resolution in device code)
__device__ float  g_logits[(size_t)B_ROWS * NKEYS];  // f32 logits
__device__ __half g_qh [(size_t)B_ROWS * DK];        // f16 Q
__device__ __half g_kh [(size_t)NKEYS  * DK];        // f16 keys
__device__ __half g_vth[(size_t)DV * NKEYS];         // f16 V^T
__device__ __half g_ah [(size_t)B_ROWS * NKEYS];     // f16 attn (GEMM2 A)

// ---------------------------------------------------------------------------
// helpers
// ---------------------------------------------------------------------------
__device__ __forceinline__ void mma_f16(float* c, uint32_t a0, uint32_t a1,
                                        uint32_t a2, uint32_t a3,
                                        uint32_t b0, uint32_t b1)
{
    asm volatile(
        "mma.sync.aligned.m16n8k16.row.col.f32.f16.f16.f32 "
        "{%0,%1,%2,%3}, {%4,%5,%6,%7}, {%8,%9}, {%0,%1,%2,%3};"
        : "+f"(c[0]), "+f"(c[1]), "+f"(c[2]), "+f"(c[3])
        : "r"(a0), "r"(a1), "r"(a2), "r"(a3), "r"(b0), "r"(b1));
}
__device__ __forceinline__ void ldsm_x4(uint32_t& r0, uint32_t& r1,
                                        uint32_t& r2, uint32_t& r3, uint32_t addr)
{
    asm volatile("ldmatrix.sync.aligned.m8n8.x4.shared.b16 {%0,%1,%2,%3}, [%4];"
                 : "=r"(r0), "=r"(r1), "=r"(r2), "=r"(r3) : "r"(addr));
}
__device__ __forceinline__ void cp_async16(uint32_t saddr, const void* gptr) {
    asm volatile("cp.async.ca.shared.global [%0], [%1], 16;" :: "r"(saddr), "l"(gptr));
}
#define CP_COMMIT() asm volatile("cp.async.commit_group;" ::: "memory")
#define CP_WAIT2()  asm volatile("cp.async.wait_group 2;" ::: "memory")

// ---------------------------------------------------------------------------
// f16 mma GEMM, 4-stage cp.async pipeline, LDSM fragment loads.
// C[M,N] = alpha * A[M,K] @ B[N,K]^T   (A, B f16 K-major; C f32)
// CTA tile 128x128, BK=32 (two k16 steps), 256 threads (8 warps 4x2),
// warp tile 32x64. Same mma sequence as R16 (bit-identical output).
// sel==1: A=g_qh, B=g_kh, C=g_logits (GEMM1). sel==2: A=g_ah, B=g_vth.
// ---------------------------------------------------------------------------
#define BK 32
#define LDH 40                      // halves per smem row (32 data + 8 pad)
#define STAGE_H (128 * LDH)         // halves per stage per matrix
#define STAGES 4
#define GEMM_SMEM (2 * STAGES * STAGE_H * 2)   // 81920 B -> 2 CTAs/SM

__global__ __launch_bounds__(256, 2) void mma_gemm_f16_kernel(
    float* __restrict__ C, int K, int ldc, float alpha, int sel)
{
    const __half* A;
    const __half* Bm;
    if (sel == 1) { A = g_qh; Bm = g_kh; C = g_logits; }
    else          { A = g_ah; Bm = g_vth; }

    extern __shared__ __half smem[];
    __half* As = smem;
    __half* Bs = smem + STAGES * STAGE_H;
    const uint32_t sA = (uint32_t)__cvta_generic_to_shared(As);
    const uint32_t sB = (uint32_t)__cvta_generic_to_shared(Bs);

    const int tid  = threadIdx.x;
    const int wid  = tid >> 5;
    const int lane = tid & 31;
    const int gid  = lane >> 2;
    const int tig  = lane & 3;
    const int m0w  = (wid >> 1) * 32;
    const int n0w  = (wid & 1) * 64;
    const int bm0  = blockIdx.y * 128;
    const int bn0  = blockIdx.x * 128;

    // staging: 4 threads per row, 8 halves (16 B) each -> 32 k per row
    const int grow = tid >> 2;            // 0..63
    const int gkc  = (tid & 3) * 8;       // half offset 0,8,16,24

    const __half* Ar0 = A  + (size_t)(bm0 + grow) * K + gkc;
    const __half* Ar1 = Ar0 + (size_t)64 * K;
    const __half* Br0 = Bm + (size_t)(bn0 + grow) * K + gkc;
    const __half* Br1 = Br0 + (size_t)64 * K;
    const uint32_t so0 = (uint32_t)(grow * LDH + gkc) * 2;
    const uint32_t so1 = (uint32_t)((grow + 64) * LDH + gkc) * 2;

    // ldmatrix lane->address maps (half offsets within a stage)
    // A x4: matrices (r0-7,k0-7),(r8-15,k0-7),(r0-7,k8-15),(r8-15,k8-15)
    const int rA = m0w + (lane & 7) + ((lane >> 3) & 1) * 8;
    const int cA = ((lane >> 4) & 1) * 8;
    // B x4: matrices (n0-7,k0-7),(n0-7,k8-15),(n8-15,k0-7),(n8-15,k8-15)
    const int rB = n0w + (lane & 7) + ((lane >> 4) & 1) * 8;
    const int cB = ((lane >> 3) & 1) * 8;

    float acc[2][8][4];
#pragma unroll
    for (int mi = 0; mi < 2; mi++)
#pragma unroll
        for (int ni = 0; ni < 8; ni++)
#pragma unroll
            for (int c = 0; c < 4; c++) acc[mi][ni][c] = 0.f;

    const int niter = K / BK;

    // prologue: stages 0..STAGES-2
#pragma unroll
    for (int s = 0; s < STAGES - 1; ++s) {
        if (s < niter) {
            const int k0 = s * BK;
            const uint32_t ob = (uint32_t)(s * STAGE_H) * 2;
            cp_async16(sA + ob + so0, Ar0 + k0);
            cp_async16(sA + ob + so1, Ar1 + k0);
            cp_async16(sB + ob + so0, Br0 + k0);
            cp_async16(sB + ob + so1, Br1 + k0);
        }
        CP_COMMIT();
    }

    for (int it = 0; it < niter; ++it) {
        CP_WAIT2();
        __syncthreads();

        const int nt = it + STAGES - 1;
        if (nt < niter) {
            const int k0 = nt * BK;
            const uint32_t ob = (uint32_t)((nt % STAGES) * STAGE_H) * 2;
            cp_async16(sA + ob + so0, Ar0 + k0);
            cp_async16(sA + ob + so1, Ar1 + k0);
            cp_async16(sB + ob + so0, Br0 + k0);
            cp_async16(sB + ob + so1, Br1 + k0);
        }
        CP_COMMIT();

        const uint32_t stg = (uint32_t)((it % STAGES) * STAGE_H) * 2;
        const uint32_t aab = sA + stg;
        const uint32_t bab = sB + stg;
#pragma unroll
        for (int ks = 0; ks < 2; ks++) {        // two k16 steps per BK=32
            const int kh = ks * 16;             // k half-offset of this step
            uint32_t a0[2], a1[2], a2[2], a3[2];
#pragma unroll
            for (int mi = 0; mi < 2; mi++)
                ldsm_x4(a0[mi], a1[mi], a2[mi], a3[mi],
                        aab + (uint32_t)((rA + mi * 16) * LDH + kh + cA) * 2);
            uint32_t b0[8], b1[8];
#pragma unroll
            for (int np = 0; np < 4; np++)      // ni pairs (2 n8-tiles each)
                ldsm_x4(b0[np * 2], b1[np * 2], b0[np * 2 + 1], b1[np * 2 + 1],
                        bab + (uint32_t)((rB + np * 16) * LDH + kh + cB) * 2);
#pragma unroll
            for (int ni = 0; ni < 8; ni++)
#pragma unroll
                for (int mi = 0; mi < 2; mi++)
                    mma_f16(acc[mi][ni], a0[mi], a1[mi], a2[mi], a3[mi],
                            b0[ni], b1[ni]);
        }
    }

    // epilogue (identical layout to R10/R12/R16)
#pragma unroll
    for (int mi = 0; mi < 2; mi++) {
        const int row0 = bm0 + m0w + mi * 16 + gid;
#pragma unroll
        for (int ni = 0; ni < 8; ni++) {
            const int col = bn0 + n0w + ni * 8 + tig * 2;
            float2 v0 = make_float2(alpha * acc[mi][ni][0], alpha * acc[mi][ni][1]);
            float2 v1 = make_float2(alpha * acc[mi][ni][2], alpha * acc[mi][ni][3]);
            *(float2*)&C[(size_t)row0 * ldc + col]       = v0;
            *(float2*)&C[(size_t)(row0 + 8) * ldc + col] = v1;
        }
    }
}

// ---------------------------------------------------------------------------
// Convert Q, keys to f16 (grid-stride; 8 floats -> 8 halves per thread step)
// ---------------------------------------------------------------------------
__global__ void to_half_kernel(const float* __restrict__ q,
                               const float* __restrict__ keys)
{
    const size_t nq8 = (size_t)B_ROWS * DK / 8;
    const size_t nk8 = (size_t)NKEYS * DK / 8;
    const size_t stride = (size_t)gridDim.x * blockDim.x;
    for (size_t i = blockIdx.x * (size_t)blockDim.x + threadIdx.x;
         i < nq8; i += stride) {
        float4 v0 = ((const float4*)q)[i * 2];
        float4 v1 = ((const float4*)q)[i * 2 + 1];
        __half2* o = (__half2*)(g_qh + i * 8);
        o[0] = __floats2half2_rn(v0.x, v0.y);
        o[1] = __floats2half2_rn(v0.z, v0.w);
        o[2] = __floats2half2_rn(v1.x, v1.y);
        o[3] = __floats2half2_rn(v1.z, v1.w);
    }
    for (size_t i = blockIdx.x * (size_t)blockDim.x + threadIdx.x;
         i < nk8; i += stride) {
        float4 v0 = ((const float4*)keys)[i * 2];
        float4 v1 = ((const float4*)keys)[i * 2 + 1];
        __half2* o = (__half2*)(g_kh + i * 8);
        o[0] = __floats2half2_rn(v0.x, v0.y);
        o[1] = __floats2half2_rn(v0.z, v0.w);
        o[2] = __floats2half2_rn(v1.x, v1.y);
        o[3] = __floats2half2_rn(v1.z, v1.w);
    }
}

// ---------------------------------------------------------------------------
// V transpose to f16: g_vth[d, n] = (half)V[n, d]
// ---------------------------------------------------------------------------
__global__ void transpose_v_kernel(const float* __restrict__ V)
{
    __shared__ float t[32][33];
    const int n0 = blockIdx.x * 32;
    const int d0 = blockIdx.y * 32;
    const int x = threadIdx.x, y = threadIdx.y;
#pragma unroll
    for (int yy = y; yy < 32; yy += 8)
        t[yy][x] = V[(size_t)(n0 + yy) * DV + d0 + x];
    __syncthreads();
#pragma unroll
    for (int yy = y; yy < 32; yy += 8)
        g_vth[(size_t)(d0 + yy) * NKEYS + n0 + x] = __float2half_rn(t[x][yy]);
}

// ---------------------------------------------------------------------------
// FUSED per-row pass: one logits read; entropy -> MLP -> tau -> tau-softmax.
// Writes attn f32 to output buffer AND f16 copy to g_ah (GEMM2 operand).
// ---------------------------------------------------------------------------
__device__ __forceinline__ void mzs_combine(float& m, float& Z, float& S,
                                            float m2, float Z2, float S2)
{
    float mn = fmaxf(m, m2);
    float e1 = __expf(m - mn);
    float e2 = __expf(m2 - mn);
    Z = Z * e1 + Z2 * e2;
    S = S * e1 + S2 * e2;
    m = mn;
}

__global__ __launch_bounds__(256) void fused_row_kernel(
    const float* __restrict__ w1, const float* __restrict__ b1,
    const float* __restrict__ w2, const float* __restrict__ b2,
    float* __restrict__ attn_out, float* __restrict__ ent_out,
    float* __restrict__ tau_out)
{
    __shared__ float sw[NKEYS];
    __shared__ float sred[8];
    __shared__ float sbc[2];
    __shared__ float smr[8], szr[8], ssr[8];

    if (attn_out == nullptr) attn_out = g_logits;
    const int row = blockIdx.x;
    const int tid = threadIdx.x;
    const float4* c4 = (const float4*)(g_logits + (size_t)row * NKEYS);
    float4* s4 = (float4*)sw;

    float m = -INFINITY, Z = 0.f, S = 0.f;
#pragma unroll
    for (int i = 0; i < 4; i++) {
        const int j = tid + i * 256;
        float4 v = c4[j];
        s4[j] = v;
        float f[4] = {v.x, v.y, v.z, v.w};
#pragma unroll
        for (int e = 0; e < 4; e++) {
            float l = f[e];
            if (l > m) {
                float sc = __expf(m - l);
                Z *= sc; S *= sc; m = l;
            }
            float ex = __expf(l - m);
            Z += ex;
            S += ex * l;
        }
    }
#pragma unroll
    for (int off = 16; off; off >>= 1) {
        float m2 = __shfl_down_sync(0xffffffffu, m, off);
        float Z2 = __shfl_down_sync(0xffffffffu, Z, off);
        float S2 = __shfl_down_sync(0xffffffffu, S, off);
        mzs_combine(m, Z, S, m2, Z2, S2);
    }
    const int wid = tid >> 5, lane = tid & 31;
    if (lane == 0) { smr[wid] = m; szr[wid] = Z; ssr[wid] = S; }
    __syncthreads();

    if (tid == 0) {
        m = smr[0]; Z = szr[0]; S = ssr[0];
#pragma unroll
        for (int w = 1; w < 8; w++) mzs_combine(m, Z, S, smr[w], szr[w], ssr[w]);

        float H = m + logf(Z) - S / Z - (float)NKEYS * EPSF;
        float max_entropy = logf((float)NKEYS);
        float e = H / (max_entropy + EPSF);
        e = fminf(fmaxf(e, 0.f), 1.f);

        float acc2 = b2[0];
#pragma unroll
        for (int h = 0; h < NH; h++) {
            float z1 = e * w1[h] + b1[h];
            float g  = 0.5f * z1 * (1.f + erff(z1 * 0.70710678118654752f));
            acc2 += g * w2[h];
        }
        float sc  = 1.f / (1.f + expf(-acc2));
        float tau = TAU_MIN + (TAU_MAX - TAU_MIN) * sc;

        if (ent_out) ent_out[row] = e;
        if (tau_out) tau_out[row] = tau;
        sbc[0] = m;
        sbc[1] = 1.f / (tau + EPSF);
    }
    __syncthreads();

    const float mm   = sbc[0];
    const float itau = sbc[1];
    float z = 0.f;
#pragma unroll
    for (int i = 0; i < 4; i++) {
        const int j = tid + i * 256;
        float4 v = s4[j];
        v.x = __expf((v.x - mm) * itau);
        v.y = __expf((v.y - mm) * itau);
        v.z = __expf((v.z - mm) * itau);
        v.w = __expf((v.w - mm) * itau);
        s4[j] = v;
        z += v.x + v.y + v.z + v.w;
    }
#pragma unroll
    for (int off = 16; off; off >>= 1)
        z += __shfl_down_sync(0xffffffffu, z, off);
    if (lane == 0) sred[wid] = z;
    __syncthreads();
    if (tid == 0) {
        float t = 0.f;
#pragma unroll
        for (int w = 0; w < 8; w++) t += sred[w];
        sred[0] = 1.f / t;
    }
    __syncthreads();
    const float invz = sred[0];

    float4*  o4 = (float4*)(attn_out + (size_t)row * NKEYS);
    __half2* h2 = (__half2*)(g_ah + (size_t)row * NKEYS);
#pragma unroll
    for (int i = 0; i < 4; i++) {
        const int j = tid + i * 256;
        float4 v = s4[j];
        v.x *= invz; v.y *= invz; v.z *= invz; v.w *= invz;
        o4[j] = v;                                   // f32 attn (output)
        h2[j * 2]     = __floats2half2_rn(v.x, v.y); // f16 attn (GEMM2 A)
        h2[j * 2 + 1] = __floats2half2_rn(v.z, v.w);
    }
}

// ---------------------------------------------------------------------------
extern "C" void kernel_launch(void* const* d_in, const int* in_sizes, int n_in,
                              void* d_out, int out_size)
{
    const float* q      = (const float*)d_in[0];
    const float* keys   = (const float*)d_in[1];
    const float* values = (const float*)d_in[2];
    const float* w1     = (const float*)d_in[3];
    const float* b1     = (const float*)d_in[4];
    const float* w2     = (const float*)d_in[5];
    const float* b2     = (const float*)d_in[6];
    float* out = (float*)d_out;

    const size_t sz_o    = (size_t)B_ROWS * DV;
    const size_t sz_attn = (size_t)B_ROWS * NKEYS;
    const size_t full_sz = sz_o + sz_attn + 2 * (size_t)B_ROWS;
    const bool full = ((size_t)out_size >= full_sz);

    float* out_o    = out;
    float* out_attn = full ? out + sz_o : nullptr;
    float* out_ent  = full ? out + sz_o + sz_attn : nullptr;
    float* out_tau  = full ? out_ent + B_ROWS : nullptr;

    const float base_scale = 0.044194173824159216f;          // 512^-0.5

    cudaFuncSetAttribute(mma_gemm_f16_kernel,
                         cudaFuncAttributeMaxDynamicSharedMemorySize, GEMM_SMEM);

    // 0a) Q, keys -> f16
    to_half_kernel<<<1024, 256>>>(q, keys);
    // 0b) V -> f16 transpose
    transpose_v_kernel<<<dim3(NKEYS / 32, DV / 32), dim3(32, 8)>>>(values);

    // 1) scaled logits -> g_logits (f16 mma, LDSM)
    mma_gemm_f16_kernel<<<dim3(NKEYS / 128, B_ROWS / 128), 256, GEMM_SMEM>>>(
        nullptr, DK, NKEYS, base_scale, 1);

    // 2+3) fused entropy + tau + tau-softmax; writes f32 attn + f16 copy
    fused_row_kernel<<<B_ROWS, 256>>>(w1, b1, w2, b2, out_attn, out_ent, out_tau);

    // 4) output = attn @ V (f16 mma: A=g_ah, B=g_vth)
    mma_gemm_f16_kernel<<<dim3(DV / 128, B_ROWS / 128), 256, GEMM_SMEM>>>(
        out_o, NKEYS, DV, 1.0f, 2);
}